// round 10
// baseline (speedup 1.0000x reference)
#include <cuda_runtime.h>
#include <cuda_bf16.h>
#include <math.h>
#include <stdint.h>

// ---------------- problem constants ----------------
#define IN_DIM   36
#define NORM_EPS 1e-5f
#define L2E      1.4426950408889634f

// folded fp32 params from prep_kernel
#define P_W1   0        // 152*36 : (in_proj @ f_out_w), conv scale folded into rows 64..143
#define P_WOUT 5472     // 64*32  : [d][o] = out_proj[o][d]*norm_w[d]
#define P_B1   7520     // 152    : fully folded biases
#define P_DSK  7840     // 8
#define P_TOTAL 7848

__device__ float g_params[P_TOTAL];

// uint4 fragment records (fh.x, fh.y, fl.x, fl.y):
//   W1 k16 : idx = nt*2 + kk          (nt<19, kk<2)  -> 38
//   W2     : idx = 38 + nt*4 + t      (nt<4,  t<4)   -> 16
#define NREC4  54
// fused-tail table (one uint2 rec per W1 n-tile, carries bias in k12/k13): 19
#define NTAIL  19

// ---------------- helpers ----------------
__device__ __forceinline__ uint32_t pk2(float a, float b) {   // lo=a, hi=b
    uint32_t r;
    asm("cvt.rn.bf16x2.f32 %0, %1, %2;" : "=r"(r) : "f"(b), "f"(a));
    return r;
}
__device__ __forceinline__ float lo16f(uint32_t p) { return __uint_as_float(p << 16); }
__device__ __forceinline__ float hi16f(uint32_t p) { return __uint_as_float(p & 0xffff0000u); }

__device__ __forceinline__ void mma16(float* c, const uint32_t* a,
                                      uint32_t b0, uint32_t b1) {
    asm volatile(
        "mma.sync.aligned.m16n8k16.row.col.f32.bf16.bf16.f32 "
        "{%0,%1,%2,%3}, {%4,%5,%6,%7}, {%8,%9}, {%0,%1,%2,%3};"
        : "+f"(c[0]), "+f"(c[1]), "+f"(c[2]), "+f"(c[3])
        : "r"(a[0]), "r"(a[1]), "r"(a[2]), "r"(a[3]), "r"(b0), "r"(b1));
}

__device__ __forceinline__ float rcpf(float v) {
    float r; asm("rcp.approx.f32 %0, %1;" : "=f"(r) : "f"(v)); return r;
}
__device__ __forceinline__ float ex2f(float v) {
    float r; asm("ex2.approx.f32 %0, %1;" : "=f"(r) : "f"(v)); return r;
}
// denominator of silu(a)*silu(b): (1+e^-a)(1+e^-b)
__device__ __forceinline__ float silu_den(float a, float b) {
    return (1.0f + __expf(-a)) * (1.0f + __expf(-b));
}
__device__ __forceinline__ float softplus1(float v) {
    return fmaxf(v, 0.0f) + __logf(1.0f + __expf(-fabsf(v)));
}

// ---------------- prep: fold weights on device ----------------
__global__ void prep_kernel(const float* __restrict__ f_out_w,
                            const float* __restrict__ f_out_b,
                            const float* __restrict__ in_proj_w,
                            const float* __restrict__ conv_w,
                            const float* __restrict__ conv_b,
                            const float* __restrict__ dt_bias,
                            const float* __restrict__ D_skip,
                            const float* __restrict__ norm_w,
                            const float* __restrict__ out_proj_w)
{
    int t = blockIdx.x * blockDim.x + threadIdx.x;
    int stride = gridDim.x * blockDim.x;
    // W1 rows: 0..63 z | 64..127 x | 128..135 B | 136..143 C | 144..151 dt
    for (int i = t; i < 152 * 36; i += stride) {
        int j = i / 36, k = i % 36;
        float s = 0.0f;
        #pragma unroll
        for (int m = 0; m < 32; m++) s += in_proj_w[j * 32 + m] * f_out_w[m * 36 + k];
        float scale = (j >= 64 && j < 144) ? conv_w[(j - 64) * 2 + 1] : 1.0f;
        g_params[P_W1 + i] = s * scale;
    }
    for (int i = t; i < 64 * 32; i += stride) {
        int d = i / 32, o = i % 32;
        g_params[P_WOUT + i] = out_proj_w[o * 64 + d] * norm_w[d];
    }
    for (int i = t; i < 152; i += stride) {
        float s = 0.0f;
        #pragma unroll
        for (int m = 0; m < 32; m++) s += in_proj_w[i * 32 + m] * f_out_b[m];
        float b;
        if (i < 64)       b = s;
        else if (i < 144) b = s * conv_w[(i - 64) * 2 + 1] + conv_b[i - 64];
        else              b = s + dt_bias[i - 144];
        g_params[P_B1 + i] = b;
    }
    for (int i = t; i < 8; i += stride) g_params[P_DSK + i] = D_skip[i];
}

// ---------------- main kernel: warp-MMA, register-resident ----------------
__global__ __launch_bounds__(256, 3)
void mamba_hmma_kernel(const float* __restrict__ x,
                       float* __restrict__ out, int N)
{
    __shared__ uint4    s_frag4[NREC4 * 32];    // 27.6 KB
    __shared__ uint2    s_ftail[NTAIL * 32];    // 4.75 KB (fused tail + bias)
    __shared__ float    s_dsk[8];
    __shared__ float    s_coef[8][16][8];       // [warp][row][head]
    __shared__ __align__(16) float s_xbuf[8][16][38];  // 19 KB staged x (pad 38 = conflict-free)

    const int tid  = threadIdx.x;
    const int lane = tid & 31;
    const int q    = lane & 3;
    const int g    = lane >> 2;
    const int w    = tid >> 5;

    // ---- build uint4 fragment table (fh01, fh23, fl01, fl23) ----
    for (int idx = tid; idx < NREC4 * 32; idx += 256) {
        int rec = idx >> 5, ln = idx & 31;
        int lq = ln & 3, lg = ln >> 2;
        float v0, v1, v2, v3;
        if (rec < 38) {
            int nt = rec >> 1, kk = rec & 1;
            int ch = nt * 8 + lg;
            int k0 = kk * 16 + 2 * lq;
            const float* wr = g_params + P_W1 + ch * 36;
            v0 = wr[k0]; v1 = wr[k0 + 1]; v2 = wr[k0 + 8]; v3 = wr[k0 + 9];
        } else {
            int r2 = rec - 38;
            int nt = r2 >> 2, t = r2 & 3;
            int o = nt * 8 + lg;
            int k0 = t * 16 + 2 * lq;
            const float* w2 = g_params + P_WOUT;
            v0 = w2[(k0    ) * 32 + o];
            v1 = w2[(k0 + 1) * 32 + o];
            v2 = w2[(k0 + 8) * 32 + o];
            v3 = w2[(k0 + 9) * 32 + o];
        }
        uint32_t h01 = pk2(v0, v1), h23 = pk2(v2, v3);
        uint32_t l01 = pk2(v0 - lo16f(h01), v1 - hi16f(h01));
        uint32_t l23 = pk2(v2 - lo16f(h23), v3 - hi16f(h23));
        s_frag4[idx] = make_uint4(h01, h23, l01, l23);
    }
    // ---- fused-tail table ----
    // b0 (k 0..7):  lq<2 -> Wh_t   ; lq>=2 -> Wl_t
    // b1 (k 8..15): lq<2 -> Wh_t   ; lq==2 -> (bh,bl) bias ; lq==3 -> 0
    for (int idx = tid; idx < NTAIL * 32; idx += 256) {
        int nt = idx >> 5, ln = idx & 31;
        int lq = ln & 3, lg = ln >> 2;
        const float* wr = g_params + P_W1 + (nt * 8 + lg) * 36;
        int i = (lq & 1) * 2;
        float v0 = wr[32 + i], v1 = wr[33 + i];
        uint32_t h = pk2(v0, v1);
        uint32_t l = pk2(v0 - lo16f(h), v1 - hi16f(h));
        float b = g_params[P_B1 + nt * 8 + lg];
        uint32_t bh = pk2(b, 0.f);
        uint32_t bias = pk2(lo16f(bh), b - lo16f(bh));   // (bh, bl)
        uint32_t b0 = (lq < 2) ? h : l;
        uint32_t b1 = (lq < 2) ? h : ((lq == 2) ? bias : 0u);
        s_ftail[idx] = make_uint2(b0, b1);
    }
    if (tid < 8) s_dsk[tid] = g_params[P_DSK + tid];
    __syncthreads();

    const int warp_global = blockIdx.x * 8 + w;
    const int nwarps = gridDim.x * 8;
    const int nchunks = (N + 15) >> 4;
    const uint32_t ones2 = pk2(1.0f, 1.0f);

    for (int chk = warp_global; chk < nchunks; chk += nwarps) {
        const int base_row = chk << 4;
        const int r0 = base_row + g;
        const int r1 = r0 + 8;
        const bool p0 = r0 < N, p1 = r1 < N;

        // ---- stage 16 rows of x (576 floats, contiguous) via coalesced LDG.128 ----
        // stores as 2x STS.64 (row stride 152 B is 8-aligned, not 16)
        {
            const float4* xs = (const float4*)(x + (size_t)base_row * IN_DIM);
            const int lim4 = (min(N - base_row, 16) * IN_DIM) >> 2;   // #float4 valid
            #pragma unroll
            for (int it = 0; it < 5; it++) {
                int j = lane + it * 32;
                if (j < 144) {
                    float4 v = (j < lim4) ? xs[j] : make_float4(0.f, 0.f, 0.f, 0.f);
                    int row = (j * 4) / IN_DIM;
                    int col = (j * 4) - row * IN_DIM;       // multiple of 4
                    *(float2*)&s_xbuf[w][row][col]     = make_float2(v.x, v.y);
                    *(float2*)&s_xbuf[w][row][col + 2] = make_float2(v.z, v.w);
                }
            }
            __syncwarp();
        }

        // ---- A1 fragments: split-bf16 of x rows g, g+8 (k = 0..31) ----
        uint32_t ah[8], al[8];
        #pragma unroll
        for (int kk = 0; kk < 2; kk++) {
            int c  = kk * 16 + 2 * q;
            int c2 = c + 8;
            float2 x00 = *(const float2*)&s_xbuf[w][g][c];
            float2 x10 = *(const float2*)&s_xbuf[w][g + 8][c];
            float2 x02 = *(const float2*)&s_xbuf[w][g][c2];
            float2 x12 = *(const float2*)&s_xbuf[w][g + 8][c2];
            uint32_t h;
            h = pk2(x00.x, x00.y); ah[kk*4+0] = h;
            al[kk*4+0] = pk2(x00.x - lo16f(h), x00.y - hi16f(h));
            h = pk2(x10.x, x10.y); ah[kk*4+1] = h;
            al[kk*4+1] = pk2(x10.x - lo16f(h), x10.y - hi16f(h));
            h = pk2(x02.x, x02.y); ah[kk*4+2] = h;
            al[kk*4+2] = pk2(x02.x - lo16f(h), x02.y - hi16f(h));
            h = pk2(x12.x, x12.y); ah[kk*4+3] = h;
            al[kk*4+3] = pk2(x12.x - lo16f(h), x12.y - hi16f(h));
        }
        // ---- fused tail A-frag (k = 32..35 + bias-one lanes) ----
        // a0/a1 (k 0..7): xh_t ; a2/a3 (k 8..15): q<2 -> xl_t, q==2 -> (1,1), q==3 -> 0
        uint32_t at[4];
        {
            int c = 32 + ((q & 1) << 1);
            float2 x0 = *(const float2*)&s_xbuf[w][g][c];
            float2 x1 = *(const float2*)&s_xbuf[w][g + 8][c];
            uint32_t h0 = pk2(x0.x, x0.y);
            uint32_t h1 = pk2(x1.x, x1.y);
            at[0] = h0;
            at[1] = h1;
            uint32_t l0 = pk2(x0.x - lo16f(h0), x0.y - hi16f(h0));
            uint32_t l1 = pk2(x1.x - lo16f(h1), x1.y - hi16f(h1));
            at[2] = (q < 2) ? l0 : ((q == 2) ? ones2 : 0u);
            at[3] = (q < 2) ? l1 : ((q == 2) ? ones2 : 0u);
        }

        // GEMM1 for one n-tile: zero-init, 2 k16 chunks x 3 split terms + fused tail
        #define GEMM1_NT(nt, c) do {                                          \
            c[0] = 0.f; c[1] = 0.f; c[2] = 0.f; c[3] = 0.f;                   \
            _Pragma("unroll")                                                 \
            for (int kk = 0; kk < 2; kk++) {                                  \
                uint4 f = s_frag4[((nt) * 2 + kk) * 32 + lane];               \
                mma16(c, ah + kk * 4, f.x, f.y);                              \
                mma16(c, ah + kk * 4, f.z, f.w);                              \
                mma16(c, al + kk * 4, f.x, f.y);                              \
            }                                                                 \
            {                                                                 \
                uint2 ft = s_ftail[(nt) * 32 + lane];                         \
                mma16(c, at, ft.x, ft.y);                                     \
            }                                                                 \
        } while (0)

        // ---- B, C, dt n-tiles (16,17,18) ----
        float cB[4], cC[4], cD[4];
        GEMM1_NT(16, cB);
        GEMM1_NT(17, cC);
        GEMM1_NT(18, cD);

        // bc per row: 4 silu-pairs, ONE rcp (batched inverse)
        float pr0, pr1;
        {
            float n0 = cB[0] * cC[0], n1 = cB[1] * cC[1];
            float n2 = cB[2] * cC[2], n3 = cB[3] * cC[3];
            float d0 = silu_den(cB[0], cC[0]);
            float d1 = silu_den(cB[1], cC[1]);
            float d2 = silu_den(cB[2], cC[2]);
            float d3 = silu_den(cB[3], cC[3]);
            float p01 = d0 * d1, p23 = d2 * d3;
            float r = rcpf(p01 * p23);
            float r01 = r * p23, r23 = r * p01;
            pr0 = n0 * (d1 * r01) + n1 * (d0 * r01);
            pr1 = n2 * (d3 * r23) + n3 * (d2 * r23);
        }
        pr0 += __shfl_xor_sync(0xffffffffu, pr0, 1);
        pr0 += __shfl_xor_sync(0xffffffffu, pr0, 2);
        pr1 += __shfl_xor_sync(0xffffffffu, pr1, 1);
        pr1 += __shfl_xor_sync(0xffffffffu, pr1, 2);

        // coef[head] = softplus(dt)*bc + D_skip  -> shared scratch (per warp)
        {
            float dsk0 = s_dsk[2 * q], dsk1 = s_dsk[2 * q + 1];
            float k00 = softplus1(cD[0]) * pr0 + dsk0;
            float k01 = softplus1(cD[1]) * pr0 + dsk1;
            float k10 = softplus1(cD[2]) * pr1 + dsk0;
            float k11 = softplus1(cD[3]) * pr1 + dsk1;
            __syncwarp();
            *(float2*)&s_coef[w][g][2 * q]     = make_float2(k00, k01);
            *(float2*)&s_coef[w][g + 8][2 * q] = make_float2(k10, k11);
            __syncwarp();
        }

        // ---- z/x n-tiles -> gated y -> GEMM2 (interleaved per 16-ch chunk) ----
        float co[16];
        #pragma unroll
        for (int i = 0; i < 16; i++) co[i] = 0.0f;
        float ss0 = 0.0f, ss1 = 0.0f;

        #pragma unroll
        for (int t = 0; t < 4; t++) {
            uint32_t a2h[4], a2l[4];
            #pragma unroll
            for (int u = 0; u < 2; u++) {
                const int j = 2 * t + u;
                float cz[4], cx[4];
                GEMM1_NT(j, cz);
                GEMM1_NT(8 + j, cx);
                float cf0 = s_coef[w][g][j];
                float cf1 = s_coef[w][g + 8][j];
                // 4 silu-pairs, ONE rcp
                float n0 = cx[0] * cz[0] * cf0, n1 = cx[1] * cz[1] * cf0;
                float n2 = cx[2] * cz[2] * cf1, n3 = cx[3] * cz[3] * cf1;
                float d0 = silu_den(cx[0], cz[0]);
                float d1 = silu_den(cx[1], cz[1]);
                float d2 = silu_den(cx[2], cz[2]);
                float d3 = silu_den(cx[3], cz[3]);
                float p01 = d0 * d1, p23 = d2 * d3;
                float r = rcpf(p01 * p23);
                float r01 = r * p23, r23 = r * p01;
                float y00 = n0 * (d1 * r01);
                float y01 = n1 * (d0 * r01);
                float y10 = n2 * (d3 * r23);
                float y11 = n3 * (d2 * r23);
                ss0 += y00 * y00 + y01 * y01;
                ss1 += y10 * y10 + y11 * y11;
                uint32_t h0 = pk2(y00, y01), h1 = pk2(y10, y11);
                a2h[2*u]     = h0;
                a2h[2*u + 1] = h1;
                a2l[2*u]     = pk2(y00 - lo16f(h0), y01 - hi16f(h0));
                a2l[2*u + 1] = pk2(y10 - lo16f(h1), y11 - hi16f(h1));
            }
            #pragma unroll
            for (int nt = 0; nt < 4; nt++) {
                uint4 f = s_frag4[(38 + nt * 4 + t) * 32 + lane];
                mma16(co + nt * 4, a2h, f.x, f.y);
                mma16(co + nt * 4, a2h, f.z, f.w);
                mma16(co + nt * 4, a2l, f.x, f.y);
            }
        }
        #undef GEMM1_NT

        ss0 += __shfl_xor_sync(0xffffffffu, ss0, 1);
        ss0 += __shfl_xor_sync(0xffffffffu, ss0, 2);
        ss1 += __shfl_xor_sync(0xffffffffu, ss1, 1);
        ss1 += __shfl_xor_sync(0xffffffffu, ss1, 2);
        // fold log2(e) into the RMS scale: softmax done in ex2 domain
        float sc0 = rsqrtf(ss0 * (1.0f / 64.0f) + NORM_EPS) * L2E;
        float sc1 = rsqrtf(ss1 * (1.0f / 64.0f) + NORM_EPS) * L2E;

        // ---- RMS scale + softmax over 32 (quad reductions) + store ----
        float lg0[8], lg1[8];
        #pragma unroll
        for (int nt = 0; nt < 4; nt++) {
            lg0[nt * 2]     = co[nt * 4 + 0] * sc0;
            lg0[nt * 2 + 1] = co[nt * 4 + 1] * sc0;
            lg1[nt * 2]     = co[nt * 4 + 2] * sc1;
            lg1[nt * 2 + 1] = co[nt * 4 + 3] * sc1;
        }
        float m0 = -1e30f, m1 = -1e30f;
        #pragma unroll
        for (int i = 0; i < 8; i++) { m0 = fmaxf(m0, lg0[i]); m1 = fmaxf(m1, lg1[i]); }
        m0 = fmaxf(m0, __shfl_xor_sync(0xffffffffu, m0, 1));
        m0 = fmaxf(m0, __shfl_xor_sync(0xffffffffu, m0, 2));
        m1 = fmaxf(m1, __shfl_xor_sync(0xffffffffu, m1, 1));
        m1 = fmaxf(m1, __shfl_xor_sync(0xffffffffu, m1, 2));
        float s0 = 0.f, s1 = 0.f;
        #pragma unroll
        for (int i = 0; i < 8; i++) {
            lg0[i] = ex2f(lg0[i] - m0); s0 += lg0[i];
            lg1[i] = ex2f(lg1[i] - m1); s1 += lg1[i];
        }
        s0 += __shfl_xor_sync(0xffffffffu, s0, 1);
        s0 += __shfl_xor_sync(0xffffffffu, s0, 2);
        s1 += __shfl_xor_sync(0xffffffffu, s1, 1);
        s1 += __shfl_xor_sync(0xffffffffu, s1, 2);
        float i0 = rcpf(s0), i1 = rcpf(s1);

        if (p0) {
            float* o0 = out + (size_t)r0 * 32 + 2 * q;
            #pragma unroll
            for (int nt = 0; nt < 4; nt++)
                *(float2*)(o0 + nt * 8) = make_float2(lg0[nt*2] * i0, lg0[nt*2+1] * i0);
        }
        if (p1) {
            float* o1 = out + (size_t)r1 * 32 + 2 * q;
            #pragma unroll
            for (int nt = 0; nt < 4; nt++)
                *(float2*)(o1 + nt * 8) = make_float2(lg1[nt*2] * i1, lg1[nt*2+1] * i1);
        }
    }
}

// ---------------- launch ----------------
extern "C" void kernel_launch(void* const* d_in, const int* in_sizes, int n_in,
                              void* d_out, int out_size)
{
    const float* x         = (const float*)d_in[0];
    const float* f_out_w   = (const float*)d_in[1];
    const float* f_out_b   = (const float*)d_in[2];
    const float* in_proj_w = (const float*)d_in[3];
    const float* conv_w    = (const float*)d_in[4];
    const float* conv_b    = (const float*)d_in[5];
    const float* dt_bias   = (const float*)d_in[6];
    // d_in[7] = A_log (unused by the reference math)
    const float* D_skip    = (const float*)d_in[8];
    const float* norm_w    = (const float*)d_in[9];
    const float* out_proj_w= (const float*)d_in[10];

    int N = in_sizes[0] / IN_DIM;

    prep_kernel<<<48, 128>>>(f_out_w, f_out_b, in_proj_w, conv_w, conv_b,
                             dt_bias, D_skip, norm_w, out_proj_w);

    mamba_hmma_kernel<<<444, 256>>>(x, (float*)d_out, N);
}

// round 11
// speedup vs baseline: 1.0269x; 1.0269x over previous
#include <cuda_runtime.h>
#include <cuda_bf16.h>
#include <math.h>
#include <stdint.h>

// ---------------- problem constants ----------------
#define IN_DIM   36
#define NORM_EPS 1e-5f
#define L2E      1.4426950408889634f

// folded fp32 params from prep_kernel
#define P_W1   0        // 152*36 : (in_proj @ f_out_w), conv scale folded into rows 64..143
#define P_WOUT 5472     // 64*32  : [d][o] = out_proj[o][d]*norm_w[d]
#define P_B1   7520     // 152    : fully folded biases
#define P_DSK  7840     // 8
#define P_TOTAL 7848

__device__ float g_params[P_TOTAL];

// k16 fragment table: W1 recs idx = nt*4 + kk*2 + m  (nt<19, kk<2)  -> 76
//                     W2 recs idx = 76 + nt*8 + kk*2 + m (nt<4,kk<4) -> 32
#define NREC16 108
// fused-tail table (one uint2 rec per W1 n-tile, carries bias in k12/k13): 19
#define NTAIL  19

// ---------------- helpers ----------------
__device__ __forceinline__ uint32_t pk2(float a, float b) {   // lo=a, hi=b
    uint32_t r;
    asm("cvt.rn.bf16x2.f32 %0, %1, %2;" : "=r"(r) : "f"(b), "f"(a));
    return r;
}
__device__ __forceinline__ float lo16f(uint32_t p) { return __uint_as_float(p << 16); }
__device__ __forceinline__ float hi16f(uint32_t p) { return __uint_as_float(p & 0xffff0000u); }

__device__ __forceinline__ void mma16(float* c, const uint32_t* a,
                                      uint32_t b0, uint32_t b1) {
    asm volatile(
        "mma.sync.aligned.m16n8k16.row.col.f32.bf16.bf16.f32 "
        "{%0,%1,%2,%3}, {%4,%5,%6,%7}, {%8,%9}, {%0,%1,%2,%3};"
        : "+f"(c[0]), "+f"(c[1]), "+f"(c[2]), "+f"(c[3])
        : "r"(a[0]), "r"(a[1]), "r"(a[2]), "r"(a[3]), "r"(b0), "r"(b1));
}
// first MMA of an accumulator: D = A*B + 0 (no init movs; C = zeros -> RZ)
__device__ __forceinline__ void mma16_init(float* c, const uint32_t* a,
                                           uint32_t b0, uint32_t b1) {
    asm volatile(
        "mma.sync.aligned.m16n8k16.row.col.f32.bf16.bf16.f32 "
        "{%0,%1,%2,%3}, {%4,%5,%6,%7}, {%8,%9}, {%10,%10,%10,%10};"
        : "=f"(c[0]), "=f"(c[1]), "=f"(c[2]), "=f"(c[3])
        : "r"(a[0]), "r"(a[1]), "r"(a[2]), "r"(a[3]), "r"(b0), "r"(b1),
          "f"(0.0f));
}

__device__ __forceinline__ float rcpf(float v) {
    float r; asm("rcp.approx.f32 %0, %1;" : "=f"(r) : "f"(v)); return r;
}
__device__ __forceinline__ float ex2f(float v) {
    float r; asm("ex2.approx.f32 %0, %1;" : "=f"(r) : "f"(v)); return r;
}
// denominator of silu(a)*silu(b): (1+e^-a)(1+e^-b)
__device__ __forceinline__ float silu_den(float a, float b) {
    return (1.0f + __expf(-a)) * (1.0f + __expf(-b));
}
__device__ __forceinline__ float softplus1(float v) {
    return fmaxf(v, 0.0f) + __logf(1.0f + __expf(-fabsf(v)));
}

// ---------------- prep: fold weights on device ----------------
__global__ void prep_kernel(const float* __restrict__ f_out_w,
                            const float* __restrict__ f_out_b,
                            const float* __restrict__ in_proj_w,
                            const float* __restrict__ conv_w,
                            const float* __restrict__ conv_b,
                            const float* __restrict__ dt_bias,
                            const float* __restrict__ D_skip,
                            const float* __restrict__ norm_w,
                            const float* __restrict__ out_proj_w)
{
    int t = blockIdx.x * blockDim.x + threadIdx.x;
    int stride = gridDim.x * blockDim.x;
    // W1 rows: 0..63 z | 64..127 x | 128..135 B | 136..143 C | 144..151 dt
    for (int i = t; i < 152 * 36; i += stride) {
        int j = i / 36, k = i % 36;
        float s = 0.0f;
        #pragma unroll
        for (int m = 0; m < 32; m++) s += in_proj_w[j * 32 + m] * f_out_w[m * 36 + k];
        float scale = (j >= 64 && j < 144) ? conv_w[(j - 64) * 2 + 1] : 1.0f;
        g_params[P_W1 + i] = s * scale;
    }
    for (int i = t; i < 64 * 32; i += stride) {
        int d = i / 32, o = i % 32;
        g_params[P_WOUT + i] = out_proj_w[o * 64 + d] * norm_w[d];
    }
    for (int i = t; i < 152; i += stride) {
        float s = 0.0f;
        #pragma unroll
        for (int m = 0; m < 32; m++) s += in_proj_w[i * 32 + m] * f_out_b[m];
        float b;
        if (i < 64)       b = s;
        else if (i < 144) b = s * conv_w[(i - 64) * 2 + 1] + conv_b[i - 64];
        else              b = s + dt_bias[i - 144];
        g_params[P_B1 + i] = b;
    }
    for (int i = t; i < 8; i += stride) g_params[P_DSK + i] = D_skip[i];
}

// ---------------- main kernel: warp-MMA, register-resident ----------------
__global__ __launch_bounds__(256, 3)
void mamba_hmma_kernel(const float* __restrict__ x,
                       float* __restrict__ out, int N)
{
    __shared__ uint2    s_frag [NREC16 * 32];   // 27.6 KB
    __shared__ uint2    s_ftail[NTAIL  * 32];   // 4.75 KB (fused tail + bias)
    __shared__ float    s_dsk[8];
    __shared__ float    s_coef[8][16][8];       // [warp][row][head]

    const int tid  = threadIdx.x;
    const int lane = tid & 31;
    const int q    = lane & 3;
    const int g    = lane >> 2;
    const int w    = tid >> 5;

    // ---- build k16 fragment table ----
    for (int idx = tid; idx < NREC16 * 32; idx += 256) {
        int rec = idx >> 5, ln = idx & 31;
        int lq = ln & 3, lg = ln >> 2;
        float v0, v1, v2, v3;
        int m;
        if (rec < 76) {
            int nt = rec >> 2, rem = rec & 3;
            int kk = rem >> 1; m = rem & 1;
            int ch = nt * 8 + lg;
            int k0 = kk * 16 + 2 * lq;
            const float* wr = g_params + P_W1 + ch * 36;
            v0 = wr[k0]; v1 = wr[k0 + 1]; v2 = wr[k0 + 8]; v3 = wr[k0 + 9];
        } else {
            int r2 = rec - 76;
            int nt = r2 >> 3, rem = r2 & 7;
            int kk = rem >> 1; m = rem & 1;
            int o = nt * 8 + lg;
            int k0 = kk * 16 + 2 * lq;
            const float* w2 = g_params + P_WOUT;
            v0 = w2[(k0    ) * 32 + o];
            v1 = w2[(k0 + 1) * 32 + o];
            v2 = w2[(k0 + 8) * 32 + o];
            v3 = w2[(k0 + 9) * 32 + o];
        }
        uint32_t h01 = pk2(v0, v1), h23 = pk2(v2, v3);
        uint32_t r0, r1;
        if (m == 0) { r0 = h01; r1 = h23; }
        else {
            r0 = pk2(v0 - lo16f(h01), v1 - hi16f(h01));
            r1 = pk2(v2 - lo16f(h23), v3 - hi16f(h23));
        }
        s_frag[idx] = make_uint2(r0, r1);
    }
    // ---- fused-tail table ----
    // b0 (k 0..7):  lq<2 -> Wh_t   ; lq>=2 -> Wl_t
    // b1 (k 8..15): lq<2 -> Wh_t   ; lq==2 -> (bh,bl) bias ; lq==3 -> 0
    for (int idx = tid; idx < NTAIL * 32; idx += 256) {
        int nt = idx >> 5, ln = idx & 31;
        int lq = ln & 3, lg = ln >> 2;
        const float* wr = g_params + P_W1 + (nt * 8 + lg) * 36;
        int i = (lq & 1) * 2;
        float v0 = wr[32 + i], v1 = wr[33 + i];
        uint32_t h = pk2(v0, v1);
        uint32_t l = pk2(v0 - lo16f(h), v1 - hi16f(h));
        float b = g_params[P_B1 + nt * 8 + lg];
        uint32_t bh = pk2(b, 0.f);
        uint32_t bias = pk2(lo16f(bh), b - lo16f(bh));   // (bh, bl)
        uint32_t b0 = (lq < 2) ? h : l;
        uint32_t b1 = (lq < 2) ? h : ((lq == 2) ? bias : 0u);
        s_ftail[idx] = make_uint2(b0, b1);
    }
    if (tid < 8) s_dsk[tid] = g_params[P_DSK + tid];
    __syncthreads();

    const int warp_global = blockIdx.x * 8 + w;
    const int nwarps = gridDim.x * 8;
    const int nchunks = (N + 15) >> 4;
    const uint32_t ones2 = pk2(1.0f, 1.0f);

    for (int chk = warp_global; chk < nchunks; chk += nwarps) {
        const int r0 = (chk << 4) + g;
        const int r1 = r0 + 8;
        const bool p0 = r0 < N, p1 = r1 < N;
        const float* rp0 = x + (size_t)r0 * IN_DIM;
        const float* rp1 = x + (size_t)r1 * IN_DIM;

        // ---- A1 fragments: split-bf16 of x rows r0, r1 (k = 0..31) ----
        uint32_t ah[8], al[8];
        #pragma unroll
        for (int kk = 0; kk < 2; kk++) {
            int c  = kk * 16 + 2 * q;
            int c2 = c + 8;
            float2 x00 = p0 ? *(const float2*)(rp0 + c)  : make_float2(0.f, 0.f);
            float2 x10 = p1 ? *(const float2*)(rp1 + c)  : make_float2(0.f, 0.f);
            float2 x02 = p0 ? *(const float2*)(rp0 + c2) : make_float2(0.f, 0.f);
            float2 x12 = p1 ? *(const float2*)(rp1 + c2) : make_float2(0.f, 0.f);
            uint32_t h;
            h = pk2(x00.x, x00.y); ah[kk*4+0] = h;
            al[kk*4+0] = pk2(x00.x - lo16f(h), x00.y - hi16f(h));
            h = pk2(x10.x, x10.y); ah[kk*4+1] = h;
            al[kk*4+1] = pk2(x10.x - lo16f(h), x10.y - hi16f(h));
            h = pk2(x02.x, x02.y); ah[kk*4+2] = h;
            al[kk*4+2] = pk2(x02.x - lo16f(h), x02.y - hi16f(h));
            h = pk2(x12.x, x12.y); ah[kk*4+3] = h;
            al[kk*4+3] = pk2(x12.x - lo16f(h), x12.y - hi16f(h));
        }
        // ---- fused tail A-frag (k = 32..35 + bias-one lanes) ----
        // a0/a1 (k 0..7): xh_t ; a2/a3 (k 8..15): q<2 -> xl_t, q==2 -> (1,1), q==3 -> 0
        uint32_t at[4];
        {
            int c = 32 + ((q & 1) << 1);
            float2 x0 = p0 ? *(const float2*)(rp0 + c) : make_float2(0.f, 0.f);
            float2 x1 = p1 ? *(const float2*)(rp1 + c) : make_float2(0.f, 0.f);
            uint32_t h0 = pk2(x0.x, x0.y);
            uint32_t h1 = pk2(x1.x, x1.y);
            at[0] = h0;
            at[1] = h1;
            uint32_t l0 = pk2(x0.x - lo16f(h0), x0.y - hi16f(h0));
            uint32_t l1 = pk2(x1.x - lo16f(h1), x1.y - hi16f(h1));
            at[2] = (q < 2) ? l0 : ((q == 2) ? ones2 : 0u);
            at[3] = (q < 2) ? l1 : ((q == 2) ? ones2 : 0u);
        }

        // GEMM1 for one n-tile: first MMA inits (C=0), 2 k16 chunks x 3 terms + fused tail
        #define GEMM1_NT(nt, c) do {                                          \
            {                                                                 \
                uint2 fh = s_frag[((nt) * 4 + 0) * 32 + lane];                \
                uint2 fl = s_frag[((nt) * 4 + 1) * 32 + lane];                \
                mma16_init(c, ah, fh.x, fh.y);                                \
                mma16(c, ah, fl.x, fl.y);                                     \
                mma16(c, al, fh.x, fh.y);                                     \
            }                                                                 \
            {                                                                 \
                uint2 fh = s_frag[((nt) * 4 + 2) * 32 + lane];                \
                uint2 fl = s_frag[((nt) * 4 + 3) * 32 + lane];                \
                mma16(c, ah + 4, fh.x, fh.y);                                 \
                mma16(c, ah + 4, fl.x, fl.y);                                 \
                mma16(c, al + 4, fh.x, fh.y);                                 \
            }                                                                 \
            {                                                                 \
                uint2 ft = s_ftail[(nt) * 32 + lane];                         \
                mma16(c, at, ft.x, ft.y);                                     \
            }                                                                 \
        } while (0)

        // ---- B, C, dt n-tiles (16,17,18) ----
        float cB[4], cC[4], cD[4];
        GEMM1_NT(16, cB);
        GEMM1_NT(17, cC);
        GEMM1_NT(18, cD);

        // bc per row: 4 silu-pairs, ONE rcp (batched inverse)
        float pr0, pr1;
        {
            float n0 = cB[0] * cC[0], n1 = cB[1] * cC[1];
            float n2 = cB[2] * cC[2], n3 = cB[3] * cC[3];
            float d0 = silu_den(cB[0], cC[0]);
            float d1 = silu_den(cB[1], cC[1]);
            float d2 = silu_den(cB[2], cC[2]);
            float d3 = silu_den(cB[3], cC[3]);
            float p01 = d0 * d1, p23 = d2 * d3;
            float r = rcpf(p01 * p23);
            float r01 = r * p23, r23 = r * p01;
            pr0 = n0 * (d1 * r01) + n1 * (d0 * r01);
            pr1 = n2 * (d3 * r23) + n3 * (d2 * r23);
        }
        pr0 += __shfl_xor_sync(0xffffffffu, pr0, 1);
        pr0 += __shfl_xor_sync(0xffffffffu, pr0, 2);
        pr1 += __shfl_xor_sync(0xffffffffu, pr1, 1);
        pr1 += __shfl_xor_sync(0xffffffffu, pr1, 2);

        // coef[head] = softplus(dt)*bc + D_skip  -> shared scratch (per warp)
        {
            float dsk0 = s_dsk[2 * q], dsk1 = s_dsk[2 * q + 1];
            float k00 = softplus1(cD[0]) * pr0 + dsk0;
            float k01 = softplus1(cD[1]) * pr0 + dsk1;
            float k10 = softplus1(cD[2]) * pr1 + dsk0;
            float k11 = softplus1(cD[3]) * pr1 + dsk1;
            __syncwarp();
            *(float2*)&s_coef[w][g][2 * q]     = make_float2(k00, k01);
            *(float2*)&s_coef[w][g + 8][2 * q] = make_float2(k10, k11);
            __syncwarp();
        }

        // ---- z/x n-tiles -> gated y -> GEMM2 (interleaved per 16-ch chunk) ----
        float co[16];
        float ss0 = 0.0f, ss1 = 0.0f;

        #pragma unroll
        for (int t = 0; t < 4; t++) {
            uint32_t a2h[4], a2l[4];
            #pragma unroll
            for (int u = 0; u < 2; u++) {
                const int j = 2 * t + u;
                float cz[4], cx[4];
                GEMM1_NT(j, cz);
                GEMM1_NT(8 + j, cx);
                float cf0 = s_coef[w][g][j];
                float cf1 = s_coef[w][g + 8][j];
                // 4 silu-pairs, ONE rcp
                float n0 = cx[0] * cz[0] * cf0, n1 = cx[1] * cz[1] * cf0;
                float n2 = cx[2] * cz[2] * cf1, n3 = cx[3] * cz[3] * cf1;
                float d0 = silu_den(cx[0], cz[0]);
                float d1 = silu_den(cx[1], cz[1]);
                float d2 = silu_den(cx[2], cz[2]);
                float d3 = silu_den(cx[3], cz[3]);
                float p01 = d0 * d1, p23 = d2 * d3;
                float r = rcpf(p01 * p23);
                float r01 = r * p23, r23 = r * p01;
                float y00 = n0 * (d1 * r01);
                float y01 = n1 * (d0 * r01);
                float y10 = n2 * (d3 * r23);
                float y11 = n3 * (d2 * r23);
                ss0 += y00 * y00 + y01 * y01;
                ss1 += y10 * y10 + y11 * y11;
                uint32_t h0 = pk2(y00, y01), h1 = pk2(y10, y11);
                a2h[2*u]     = h0;
                a2h[2*u + 1] = h1;
                a2l[2*u]     = pk2(y00 - lo16f(h0), y01 - hi16f(h0));
                a2l[2*u + 1] = pk2(y10 - lo16f(h1), y11 - hi16f(h1));
            }
            #pragma unroll
            for (int nt = 0; nt < 4; nt++) {
                uint2 fh = s_frag[(76 + nt * 8 + t * 2 + 0) * 32 + lane];
                uint2 fl = s_frag[(76 + nt * 8 + t * 2 + 1) * 32 + lane];
                if (t == 0) mma16_init(co + nt * 4, a2h, fh.x, fh.y);
                else        mma16(co + nt * 4, a2h, fh.x, fh.y);
                mma16(co + nt * 4, a2h, fl.x, fl.y);
                mma16(co + nt * 4, a2l, fh.x, fh.y);
            }
        }
        #undef GEMM1_NT

        ss0 += __shfl_xor_sync(0xffffffffu, ss0, 1);
        ss0 += __shfl_xor_sync(0xffffffffu, ss0, 2);
        ss1 += __shfl_xor_sync(0xffffffffu, ss1, 1);
        ss1 += __shfl_xor_sync(0xffffffffu, ss1, 2);
        // fold log2(e) into the RMS scale: softmax done in ex2 domain
        float sc0 = rsqrtf(ss0 * (1.0f / 64.0f) + NORM_EPS) * L2E;
        float sc1 = rsqrtf(ss1 * (1.0f / 64.0f) + NORM_EPS) * L2E;

        // ---- softmax over 32, max-free (|logit| <= ~11 -> ex2 args bounded) ----
        float lg0[8], lg1[8];
        float s0 = 0.f, s1 = 0.f;
        #pragma unroll
        for (int nt = 0; nt < 4; nt++) {
            lg0[nt * 2]     = ex2f(co[nt * 4 + 0] * sc0);
            lg0[nt * 2 + 1] = ex2f(co[nt * 4 + 1] * sc0);
            lg1[nt * 2]     = ex2f(co[nt * 4 + 2] * sc1);
            lg1[nt * 2 + 1] = ex2f(co[nt * 4 + 3] * sc1);
        }
        #pragma unroll
        for (int i = 0; i < 8; i++) { s0 += lg0[i]; s1 += lg1[i]; }
        s0 += __shfl_xor_sync(0xffffffffu, s0, 1);
        s0 += __shfl_xor_sync(0xffffffffu, s0, 2);
        s1 += __shfl_xor_sync(0xffffffffu, s1, 1);
        s1 += __shfl_xor_sync(0xffffffffu, s1, 2);
        float i0 = rcpf(s0), i1 = rcpf(s1);

        if (p0) {
            float* o0 = out + (size_t)r0 * 32 + 2 * q;
            #pragma unroll
            for (int nt = 0; nt < 4; nt++)
                *(float2*)(o0 + nt * 8) = make_float2(lg0[nt*2] * i0, lg0[nt*2+1] * i0);
        }
        if (p1) {
            float* o1 = out + (size_t)r1 * 32 + 2 * q;
            #pragma unroll
            for (int nt = 0; nt < 4; nt++)
                *(float2*)(o1 + nt * 8) = make_float2(lg1[nt*2] * i1, lg1[nt*2+1] * i1);
        }
    }
}

// ---------------- launch ----------------
extern "C" void kernel_launch(void* const* d_in, const int* in_sizes, int n_in,
                              void* d_out, int out_size)
{
    const float* x         = (const float*)d_in[0];
    const float* f_out_w   = (const float*)d_in[1];
    const float* f_out_b   = (const float*)d_in[2];
    const float* in_proj_w = (const float*)d_in[3];
    const float* conv_w    = (const float*)d_in[4];
    const float* conv_b    = (const float*)d_in[5];
    const float* dt_bias   = (const float*)d_in[6];
    // d_in[7] = A_log (unused by the reference math)
    const float* D_skip    = (const float*)d_in[8];
    const float* norm_w    = (const float*)d_in[9];
    const float* out_proj_w= (const float*)d_in[10];

    int N = in_sizes[0] / IN_DIM;

    prep_kernel<<<48, 128>>>(f_out_w, f_out_b, in_proj_w, conv_w, conv_b,
                             dt_bias, D_skip, norm_w, out_proj_w);

    mamba_hmma_kernel<<<444, 256>>>(x, (float*)d_out, N);
}